// round 10
// baseline (speedup 1.0000x reference)
#include <cuda_runtime.h>
#include <cuda_bf16.h>
#include <cstdint>

// ---------------------------------------------------------------------------
// SimpleCNN gated pipeline.  R7: conv2m mainloop de-bloated:
//   - B fragments pre-arranged in global (fragment-major), loaded as LDG.128
//   - A fragments via ldmatrix.x4
//   - 9-shift mainloop is __syncthreads()-free
// ---------------------------------------------------------------------------

#define NB 256

__device__ float          g_p1[NB * 32 * 32 * 32];
__device__ unsigned char  g_m2[NB * 32 * 32];
__device__ __nv_bfloat16  g_p2h[NB * 16384];
__device__ __nv_bfloat16  g_p2l[NB * 16384];
__device__ uint32_t       g_Bf[9 * 2 * 2 * 2 * 2 * 32 * 4];   // conv2 W fragments
__device__ __nv_bfloat16  g_Wh[128 * 16384];     // fc1 weights hi [j][k]
__device__ __nv_bfloat16  g_Wl[128 * 16384];
#define KSPLIT 128
__device__ float          g_part[KSPLIT * 256 * 128];

__device__ __forceinline__ void mma16816(float* d, const uint32_t* a, const uint32_t* b) {
    asm volatile(
        "mma.sync.aligned.m16n8k16.row.col.f32.bf16.bf16.f32 "
        "{%0,%1,%2,%3}, {%4,%5,%6,%7}, {%8,%9}, {%0,%1,%2,%3};"
        : "+f"(d[0]), "+f"(d[1]), "+f"(d[2]), "+f"(d[3])
        : "r"(a[0]), "r"(a[1]), "r"(a[2]), "r"(a[3]), "r"(b[0]), "r"(b[1]));
}
__device__ __forceinline__ uint32_t smem_u32(const void* p) {
    uint32_t a;
    asm("{ .reg .u64 t; cvta.to.shared.u64 t, %1; cvt.u32.u64 %0, t; }" : "=r"(a) : "l"(p));
    return a;
}
#define LDMX4(r, addr) \
    asm volatile("ldmatrix.sync.aligned.m8n8.x4.shared.b16 {%0,%1,%2,%3}, [%4];" \
        : "=r"((r)[0]), "=r"((r)[1]), "=r"((r)[2]), "=r"((r)[3]) : "r"(addr))

__device__ __forceinline__ unsigned short bfbits(__nv_bfloat16 h) {
    unsigned short s; memcpy(&s, &h, 2); return s;
}

// ===========================================================================
// Kernel 0a: W2 -> fragment-major bf16 hi/lo B for conv2m
// layout idx = ((((s*2+ks)*2+wn)*2+hl)*2+reg)*32*4 ... [lane][nt]
// ===========================================================================
__global__ void k_prepf(const float* __restrict__ W2)
{
    int i = blockIdx.x * 256 + threadIdx.x;      // 18432
    if (i >= 9 * 2 * 2 * 2 * 2 * 32 * 4) return;
    int nt   = i & 3;
    int lane = (i >> 2) & 31;
    int reg  = (i >> 7) & 1;
    int hl   = (i >> 8) & 1;
    int wn   = (i >> 9) & 1;
    int ks   = (i >> 10) & 1;
    int s    = i >> 11;
    int g = lane >> 2, t = lane & 3;
    int co  = wn * 32 + nt * 8 + g;
    int ci0 = ks * 16 + reg * 8 + 2 * t;
    float w0 = W2[co * 288 + ci0 * 9 + s];
    float w1 = W2[co * 288 + (ci0 + 1) * 9 + s];
    __nv_bfloat16 h0 = __float2bfloat16(w0);
    __nv_bfloat16 h1 = __float2bfloat16(w1);
    __nv_bfloat16 e0, e1;
    if (hl == 0) { e0 = h0; e1 = h1; }
    else {
        e0 = __float2bfloat16(w0 - __bfloat162float(h0));
        e1 = __float2bfloat16(w1 - __bfloat162float(h1));
    }
    g_Bf[i] = (uint32_t)bfbits(e0) | ((uint32_t)bfbits(e1) << 16);
}

// ===========================================================================
// Kernel 0b: split Wfc1 into bf16 hi/lo
// ===========================================================================
__global__ void k_prep_fc1(const float* __restrict__ Wfc1)
{
    int i = blockIdx.x * 256 + threadIdx.x;
    float w = Wfc1[i];
    __nv_bfloat16 hi = __float2bfloat16(w);
    __nv_bfloat16 lo = __float2bfloat16(w - __bfloat162float(hi));
    g_Wh[i] = hi;
    g_Wl[i] = lo;
}

// ===========================================================================
// Kernel 1: conv1 + gates + pool (unchanged scalar)
// ===========================================================================
__global__ __launch_bounds__(256) void k_conv1(
    const float* __restrict__ x, const int* __restrict__ cmap,
    const float* __restrict__ W1, const float* __restrict__ b1)
{
    __shared__ float xs[66 * 66];
    __shared__ unsigned char cs[64 * 64];
    __shared__ unsigned char rs[64 * 64];
    __shared__ unsigned char m1s[64 * 64];
    __shared__ unsigned char m2s[32 * 32];
    __shared__ float w1s[288];
    __shared__ float b1s[32];

    const int b = blockIdx.x, t = threadIdx.x;
    const float* xb = x + b * 4096;
    const int*   cb = cmap + b * 4096;

    for (int i = t; i < 66 * 66; i += 256) {
        int r = i / 66, c = i % 66;
        float v = 0.f;
        if (r >= 1 && r <= 64 && c >= 1 && c <= 64) v = xb[(r - 1) * 64 + (c - 1)];
        xs[i] = v;
    }
    for (int i = t; i < 4096; i += 256) cs[i] = (unsigned char)cb[i];
    for (int i = t; i < 288; i += 256) w1s[i] = W1[i];
    if (t < 32)  b1s[t] = b1[t];
    __syncthreads();

    for (int i = t; i < 4096; i += 256) {
        int c = i & 63;
        int s = cs[i];
        if (c < 63) s += cs[i + 1];
        if (c < 62) s += cs[i + 2];
        rs[i] = (unsigned char)s;
    }
    __syncthreads();
    for (int i = t; i < 4096; i += 256) {
        int r = i >> 6;
        int s = rs[i];
        if (r < 63) s += rs[i + 64];
        if (r < 62) s += rs[i + 128];
        m1s[i] = (unsigned char)(s > 1);
    }
    __syncthreads();
    for (int i = t; i < 1024; i += 256) {
        int r = i >> 5, c = i & 31;
        int s = m1s[(2 * r) * 64 + 2 * c] + m1s[(2 * r) * 64 + 2 * c + 1]
              + m1s[(2 * r + 1) * 64 + 2 * c] + m1s[(2 * r + 1) * 64 + 2 * c + 1];
        m2s[i] = (unsigned char)(s > 1);
    }
    __syncthreads();
    for (int i = t; i < 1024; i += 256) g_m2[b * 1024 + i] = m2s[i];

    float* p1b = g_p1 + b * 32768;

    for (int pp = 0; pp < 4; pp++) {
        const int pos = pp * 256 + t;
        const int py = pos >> 5, px = pos & 31;
        const bool g2 = (m2s[pos] != 0);

        float patch[4][4];
        #pragma unroll
        for (int r = 0; r < 4; r++)
            #pragma unroll
            for (int c = 0; c < 4; c++)
                patch[r][c] = xs[(2 * py + r) * 66 + (2 * px + c)];

        bool mm[2][2];
        mm[0][0] = m1s[(2 * py) * 64 + 2 * px];
        mm[0][1] = m1s[(2 * py) * 64 + 2 * px + 1];
        mm[1][0] = m1s[(2 * py + 1) * 64 + 2 * px];
        mm[1][1] = m1s[(2 * py + 1) * 64 + 2 * px + 1];

        for (int co = 0; co < 32; co++) {
            float best = 0.f;
            if (g2) {
                float wv[9];
                #pragma unroll
                for (int k = 0; k < 9; k++) wv[k] = w1s[co * 9 + k];
                const float bias = b1s[co];
                #pragma unroll
                for (int dr = 0; dr < 2; dr++)
                    #pragma unroll
                    for (int dc = 0; dc < 2; dc++) {
                        if (mm[dr][dc]) {
                            float s = bias;
                            #pragma unroll
                            for (int kr = 0; kr < 3; kr++)
                                #pragma unroll
                                for (int kc = 0; kc < 3; kc++)
                                    s += wv[kr * 3 + kc] * patch[dr + kr][dc + kc];
                            best = fmaxf(best, s);
                        }
                    }
            }
            p1b[co * 1024 + pos] = best;
        }
    }
}

// ===========================================================================
// Kernel 2: conv2 via mma.sync bf16.  Grid = NB*8, 128 threads (4 warps:
// 2 row-pairs x 2 co-halves), warp tile 64pos x 32co.
// Mainloop: ldmatrix A from smem, B fragments LDG.128 from global, no syncs.
// ===========================================================================
#define C2_PSZ  (6 * 34 * 144)       // 29376, P at smem offset 0
#define C2_BIAS 29376
#define C2_M2S  29632
#define C2_M3S  29824
#define C2_M4S  29952
#define C2_SMEM 30080

__device__ __forceinline__ void store_p2(int idx, float v) {
    __nv_bfloat16 hi = __float2bfloat16(v);
    __nv_bfloat16 lo = __float2bfloat16(v - __bfloat162float(hi));
    g_p2h[idx] = hi;
    g_p2l[idx] = lo;
}

__global__ __launch_bounds__(128, 4) void k_conv2m(const float* __restrict__ b2)
{
    extern __shared__ char smc[];
    const int bq = blockIdx.x;
    const int b = bq >> 3, q = bq & 7;
    const int tx = threadIdx.x;
    const int w = tx >> 5, lane = tx & 31;
    const int wr = w >> 1, wn = w & 1;
    const int g = lane >> 2, t = lane & 3;
    const int r0 = 4 * q;

    float* b2s = (float*)(smc + C2_BIAS);
    unsigned char* m2s = (unsigned char*)(smc + C2_M2S);
    unsigned char* m3s = (unsigned char*)(smc + C2_M3S);
    unsigned char* m4s = (unsigned char*)(smc + C2_M4S);

    for (int i = tx; i < C2_PSZ / 4; i += 128) ((uint32_t*)smc)[i] = 0;
    if (tx < 64) b2s[tx] = b2[tx];
    for (int i = tx; i < 192; i += 128) {
        int r = i >> 5, c = i & 31;
        int yr = r0 + r;
        m2s[i] = (yr < 32) ? g_m2[b * 1024 + yr * 32 + c] : (unsigned char)0;
    }
    __syncthreads();

    for (int i = tx; i < 128; i += 128) {
        int r = i >> 5, c = i & 31;
        int s = 0;
        #pragma unroll
        for (int dr = 0; dr < 3; dr++) {
            s += m2s[(r + dr) * 32 + c];
            if (c + 1 < 32) s += m2s[(r + dr) * 32 + c + 1];
            if (c + 2 < 32) s += m2s[(r + dr) * 32 + c + 2];
        }
        m3s[i] = (unsigned char)(s > 1);
    }
    {
        const float* p1b = g_p1 + b * 32768;
        int y_lo = r0 - 1; if (y_lo < 0) y_lo = 0;
        int y_hi = r0 + 4; if (y_hi > 31) y_hi = 31;
        for (int y = y_lo; y <= y_hi; y++) {
            const float* row = p1b + y * 32;
            for (int i2 = tx; i2 < 1024; i2 += 128) {
                int ci = i2 >> 5, x = i2 & 31;
                float v = row[ci * 1024 + x];
                __nv_bfloat16 hi = __float2bfloat16(v);
                __nv_bfloat16 lo = __float2bfloat16(v - __bfloat162float(hi));
                char* blk = smc + ((y - r0 + 1) * 34 + (x + 1)) * 144;
                *(__nv_bfloat16*)(blk + 2 * ci) = hi;
                *(__nv_bfloat16*)(blk + 64 + 2 * ci) = lo;
            }
        }
    }
    __syncthreads();
    if (tx < 32) {
        int gyl = tx >> 4, gx = tx & 15;
        int s = m3s[(2 * gyl) * 32 + 2 * gx] + m3s[(2 * gyl) * 32 + 2 * gx + 1]
              + m3s[(2 * gyl + 1) * 32 + 2 * gx] + m3s[(2 * gyl + 1) * 32 + 2 * gx + 1];
        m4s[tx] = (unsigned char)(s > 1);
    }
    __syncthreads();   // P + masks complete; mainloop below is sync-free

    float acc[4][4][4];
    #pragma unroll
    for (int mt = 0; mt < 4; mt++)
        #pragma unroll
        for (int nt = 0; nt < 4; nt++)
            #pragma unroll
            for (int j = 0; j < 4; j++) acc[mt][nt][j] = 0.f;

    // per-lane ldmatrix row addresses (x4: lanes 0-15 rows, 16-31 k-half 2)
    const uint32_t sb = smem_u32(smc);
    const int ml = lane & 15, kh = lane >> 4;
    uint32_t Abase[4];
    #pragma unroll
    for (int mt = 0; mt < 4; mt++)
        Abase[mt] = sb + (uint32_t)((((2 * wr + (mt >> 1)) * 34) + (mt & 1) * 16 + ml) * 144 + kh * 16);

    const uint4* pbase = (const uint4*)g_Bf;

    for (int s = 0; s < 9; s++) {
        const int sy = s / 3, sx = s - sy * 3;
        const uint32_t soff = (uint32_t)((sy * 34 + sx) * 144);
        #pragma unroll
        for (int ks = 0; ks < 2; ks++) {
            const int fo = ((s * 2 + ks) * 2 + wn) * 128 + lane;   // uint4 index
            uint4 bh0 = pbase[fo];
            uint4 bh1 = pbase[fo + 32];
            uint4 bl0 = pbase[fo + 64];
            uint4 bl1 = pbase[fo + 96];
            uint32_t Bh[4][2] = {{bh0.x, bh1.x}, {bh0.y, bh1.y}, {bh0.z, bh1.z}, {bh0.w, bh1.w}};
            uint32_t Bl[4][2] = {{bl0.x, bl1.x}, {bl0.y, bl1.y}, {bl0.z, bl1.z}, {bl0.w, bl1.w}};

            const uint32_t ao = soff + ks * 32;
            uint32_t A[4][4];
            #pragma unroll
            for (int mt = 0; mt < 4; mt++) LDMX4(A[mt], Abase[mt] + ao);
            #pragma unroll
            for (int mt = 0; mt < 4; mt++)
                #pragma unroll
                for (int nt = 0; nt < 4; nt++)
                    mma16816(acc[mt][nt], A[mt], Bh[nt]);      // ah*bh
            #pragma unroll
            for (int mt = 0; mt < 4; mt++)
                #pragma unroll
                for (int nt = 0; nt < 4; nt++)
                    mma16816(acc[mt][nt], A[mt], Bl[nt]);      // ah*bl
            #pragma unroll
            for (int mt = 0; mt < 4; mt++) LDMX4(A[mt], Abase[mt] + ao + 64);
            #pragma unroll
            for (int mt = 0; mt < 4; mt++)
                #pragma unroll
                for (int nt = 0; nt < 4; nt++)
                    mma16816(acc[mt][nt], A[mt], Bh[nt]);      // al*bh
        }
    }

    // epilogue: m3 gate + bias + relu -> pool -> m4 gate -> bf16 hi/lo store
    const int gy = 2 * q + wr;
    const int dbase = b * 16384 + gy * 16;
    #pragma unroll
    for (int mh = 0; mh < 2; mh++) {
        #pragma unroll
        for (int nt = 0; nt < 4; nt++) {
            const int co = wn * 32 + nt * 8 + 2 * t;
            const float bias0 = b2s[co];
            const float bias1 = b2s[co + 1];
            float v0[2], v1[2], v2[2], v3[2];
            #pragma unroll
            for (int mp = 0; mp < 2; mp++) {
                const int mt = mh + 2 * mp;
                const int mrow = (2 * wr + mp) * 32 + mh * 16 + g;
                const bool g3a = m3s[mrow] != 0;
                const bool g3b = m3s[mrow + 8] != 0;
                v0[mp] = g3a ? fmaxf(acc[mt][nt][0] + bias0, 0.f) : 0.f;
                v1[mp] = g3a ? fmaxf(acc[mt][nt][1] + bias1, 0.f) : 0.f;
                v2[mp] = g3b ? fmaxf(acc[mt][nt][2] + bias0, 0.f) : 0.f;
                v3[mp] = g3b ? fmaxf(acc[mt][nt][3] + bias1, 0.f) : 0.f;
            }
            float o0 = fmaxf(v0[0], v0[1]);
            float o1 = fmaxf(v1[0], v1[1]);
            float o2 = fmaxf(v2[0], v2[1]);
            float o3 = fmaxf(v3[0], v3[1]);
            o0 = fmaxf(o0, __shfl_xor_sync(0xffffffffu, o0, 4));
            o1 = fmaxf(o1, __shfl_xor_sync(0xffffffffu, o1, 4));
            o2 = fmaxf(o2, __shfl_xor_sync(0xffffffffu, o2, 4));
            o3 = fmaxf(o3, __shfl_xor_sync(0xffffffffu, o3, 4));
            if ((lane & 4) == 0) {
                const int gxa = mh * 8 + (g >> 1);
                const int gxb = gxa + 4;
                const bool g4a = m4s[wr * 16 + gxa] != 0;
                const bool g4b = m4s[wr * 16 + gxb] != 0;
                store_p2(dbase + co * 256 + gxa,       g4a ? o0 : 0.f);
                store_p2(dbase + (co + 1) * 256 + gxa, g4a ? o1 : 0.f);
                store_p2(dbase + co * 256 + gxb,       g4b ? o2 : 0.f);
                store_p2(dbase + (co + 1) * 256 + gxb, g4b ? o3 : 0.f);
            }
        }
    }
}

// ===========================================================================
// Kernel 3: FC1 via mma.sync bf16 (3-term hi/lo), global-direct fragments.
// ===========================================================================
__global__ __launch_bounds__(256) void k_fc1m()
{
    const int ks = blockIdx.x;
    const int tx = threadIdx.x;
    const int warp = tx >> 5, lane = tx & 31;
    const int g = lane >> 2, t = lane & 3;
    const int wm = warp >> 1, wn = warp & 1;
    const int row0 = wm * 64, col0 = wn * 64;
    const int k0 = ks * 128;

    float acc[4][8][4];
    #pragma unroll
    for (int mt = 0; mt < 4; mt++)
        #pragma unroll
        for (int nt = 0; nt < 8; nt++)
            #pragma unroll
            for (int j = 0; j < 4; j++) acc[mt][nt][j] = 0.f;

    #pragma unroll 2
    for (int kk = 0; kk < 8; kk++) {
        const int kb = k0 + kk * 16;
        uint32_t Ah[4][4], Al[4][4];
        #pragma unroll
        for (int mt = 0; mt < 4; mt++) {
            const int r = row0 + mt * 16 + g;
            const __nv_bfloat16* ph = g_p2h + r * 16384 + kb + 2 * t;
            const __nv_bfloat16* pl = g_p2l + r * 16384 + kb + 2 * t;
            Ah[mt][0] = *(const uint32_t*)(ph);
            Ah[mt][1] = *(const uint32_t*)(ph + 8 * 16384);
            Ah[mt][2] = *(const uint32_t*)(ph + 8);
            Ah[mt][3] = *(const uint32_t*)(ph + 8 * 16384 + 8);
            Al[mt][0] = *(const uint32_t*)(pl);
            Al[mt][1] = *(const uint32_t*)(pl + 8 * 16384);
            Al[mt][2] = *(const uint32_t*)(pl + 8);
            Al[mt][3] = *(const uint32_t*)(pl + 8 * 16384 + 8);
        }
        #pragma unroll
        for (int term = 0; term < 3; term++) {
            const __nv_bfloat16* wbase = (term == 1) ? g_Wl : g_Wh;
            uint32_t Bf[8][2];
            #pragma unroll
            for (int nt = 0; nt < 8; nt++) {
                const int j = col0 + nt * 8 + g;
                const __nv_bfloat16* pb = wbase + j * 16384 + kb + 2 * t;
                Bf[nt][0] = *(const uint32_t*)(pb);
                Bf[nt][1] = *(const uint32_t*)(pb + 8);
            }
            #pragma unroll
            for (int mt = 0; mt < 4; mt++) {
                const uint32_t* A = (term == 2) ? Al[mt] : Ah[mt];
                #pragma unroll
                for (int nt = 0; nt < 8; nt++)
                    mma16816(acc[mt][nt], A, Bf[nt]);
            }
        }
    }

    float* dst = g_part + ks * 32768;
    #pragma unroll
    for (int mt = 0; mt < 4; mt++) {
        const int r = row0 + mt * 16 + g;
        #pragma unroll
        for (int nt = 0; nt < 8; nt++) {
            const int c = col0 + nt * 8 + 2 * t;
            *(float2*)(dst + r * 128 + c)       = make_float2(acc[mt][nt][0], acc[mt][nt][1]);
            *(float2*)(dst + (r + 8) * 128 + c) = make_float2(acc[mt][nt][2], acc[mt][nt][3]);
        }
    }
}

// ===========================================================================
// Kernel 4: reduce 128 partials + bfc1 + relu + FC2 (512 threads)
// ===========================================================================
__global__ __launch_bounds__(512) void k_fc2(
    const float* __restrict__ bfc1, const float* __restrict__ Wfc2,
    const float* __restrict__ bfc2, float* __restrict__ out)
{
    __shared__ float part[4][128];
    __shared__ float hs[128];
    const int b = blockIdx.x, t = threadIdx.x;
    const int j = t & 127, seg = t >> 7;

    float s = 0.f;
    #pragma unroll 8
    for (int ks = seg * 32; ks < seg * 32 + 32; ks++)
        s += g_part[ks * 32768 + b * 128 + j];
    part[seg][j] = s;
    __syncthreads();

    if (t < 128) {
        float v = part[0][t] + part[1][t] + part[2][t] + part[3][t] + bfc1[t];
        hs[t] = fmaxf(v, 0.f);
    }
    __syncthreads();

    if (t < 10) {
        float a = bfc2[t];
        #pragma unroll 8
        for (int jj = 0; jj < 128; jj++) a += hs[jj] * Wfc2[t * 128 + jj];
        out[b * 10 + t] = a;
    }
}

// ===========================================================================
extern "C" void kernel_launch(void* const* d_in, const int* in_sizes, int n_in,
                              void* d_out, int out_size)
{
    const float* x    = (const float*)d_in[0];
    const int*   cmap = (const int*)  d_in[1];
    const float* W1   = (const float*)d_in[2];
    const float* b1   = (const float*)d_in[3];
    const float* W2   = (const float*)d_in[4];
    const float* b2   = (const float*)d_in[5];
    const float* Wfc1 = (const float*)d_in[6];
    const float* bfc1 = (const float*)d_in[7];
    const float* Wfc2 = (const float*)d_in[8];
    const float* bfc2 = (const float*)d_in[9];
    float* out = (float*)d_out;

    cudaFuncSetAttribute(k_conv2m, cudaFuncAttributeMaxDynamicSharedMemorySize, C2_SMEM);

    k_prepf<<<72, 256>>>(W2);
    k_prep_fc1<<<8192, 256>>>(Wfc1);
    k_conv1<<<NB, 256>>>(x, cmap, W1, b1);
    k_conv2m<<<NB * 8, 128, C2_SMEM>>>(b2);
    k_fc1m<<<KSPLIT, 256>>>();
    k_fc2<<<NB, 512>>>(bfc1, Wfc2, bfc2, out);
}